// round 9
// baseline (speedup 1.0000x reference)
#include <cuda_runtime.h>

#define NSRC 100000
#define NTGT 100000
#define NEDGE 1600000
#define NTOT (NSRC + NTGT)
#define E4 (NEDGE / 4)

// ---------------- scratch: one contiguous zero-init block + rest ------------
struct ZeroBlock {
    int   deg_s[NSRC];
    int   deg_t[NTGT];
    float a[3][NSRC];   // a1,a2,a3 = S^T 1_t, S^T T^T 1_s, S^T T^T S^T 1_t
    float b[3][NTGT];   // b1,b2,b3 (mirror)
    float psums[4];     // sum(a1), sum(a2), sum(b1), sum(b2)
    float sum;          // final node-sum
};
__device__ ZeroBlock gz;
__device__ float g_pa[NSRC];     // a_r * inv_s (staging, fully overwritten)
__device__ float g_pb[NTGT];
__device__ float g_Q[8][64];     // level-0 coefficient vectors (fully written)
__device__ float g_acc;          // bias scalar contribution (fully written)

__device__ __forceinline__ float rcp_deg(int d) {
    return 1.0f / (float)max(d, 1);
}

// ---------------- degrees: 4 edges/thread, int4 dst loads -------------------
__global__ void deg_kernel(const int4* __restrict__ s2t_dst,
                           const int4* __restrict__ t2s_dst) {
    int i = blockIdx.x * blockDim.x + threadIdx.x;
    if (i < E4) {
        int4 d = __ldg(s2t_dst + i);
        atomicAdd(&gz.deg_t[d.x], 1);
        atomicAdd(&gz.deg_t[d.y], 1);
        atomicAdd(&gz.deg_t[d.z], 1);
        atomicAdd(&gz.deg_t[d.w], 1);
    } else if (i < 2 * E4) {
        int4 d = __ldg(t2s_dst + (i - E4));
        atomicAdd(&gz.deg_s[d.x], 1);
        atomicAdd(&gz.deg_s[d.y], 1);
        atomicAdd(&gz.deg_s[d.z], 1);
        atomicAdd(&gz.deg_s[d.w], 1);
    }
}

// ---------------- spmv1: a1[src] += rcp(deg_t[dst]) (and b1 mirror) ---------
__global__ void spmv1_kernel(const int4* __restrict__ s2t,
                             const int4* __restrict__ t2s) {
    int i = blockIdx.x * blockDim.x + threadIdx.x;
    if (i < E4) {
        int4 s = __ldg(s2t + i);
        int4 d = __ldg(s2t + E4 + i);
        float vx = rcp_deg(__ldg(&gz.deg_t[d.x]));
        float vy = rcp_deg(__ldg(&gz.deg_t[d.y]));
        float vz = rcp_deg(__ldg(&gz.deg_t[d.z]));
        float vw = rcp_deg(__ldg(&gz.deg_t[d.w]));
        atomicAdd(&gz.a[0][s.x], vx);
        atomicAdd(&gz.a[0][s.y], vy);
        atomicAdd(&gz.a[0][s.z], vz);
        atomicAdd(&gz.a[0][s.w], vw);
    } else if (i < 2 * E4) {
        int e = i - E4;
        int4 s = __ldg(t2s + e);
        int4 d = __ldg(t2s + E4 + e);
        float vx = rcp_deg(__ldg(&gz.deg_s[d.x]));
        float vy = rcp_deg(__ldg(&gz.deg_s[d.y]));
        float vz = rcp_deg(__ldg(&gz.deg_s[d.z]));
        float vw = rcp_deg(__ldg(&gz.deg_s[d.w]));
        atomicAdd(&gz.b[0][s.x], vx);
        atomicAdd(&gz.b[0][s.y], vy);
        atomicAdd(&gz.b[0][s.z], vz);
        atomicAdd(&gz.b[0][s.w], vw);
    }
}

// ---------------- prep(r): pa = a[r]*inv_s, pb = b[r]*inv_t, + fold sums ----
__global__ void prep_kernel(int r) {
    int i = blockIdx.x * blockDim.x + threadIdx.x;
    float va = 0.0f, vb = 0.0f;
    if (i < NSRC) {
        va = gz.a[r][i];
        g_pa[i] = va * rcp_deg(gz.deg_s[i]);
    }
    if (i < NTGT) {
        vb = gz.b[r][i];
        g_pb[i] = vb * rcp_deg(gz.deg_t[i]);
    }
    #pragma unroll
    for (int off = 16; off; off >>= 1) {
        va += __shfl_down_sync(0xffffffffu, va, off);
        vb += __shfl_down_sync(0xffffffffu, vb, off);
    }
    if ((threadIdx.x & 31) == 0) {
        atomicAdd(&gz.psums[r], va);        // sum(a1)->[0], sum(a2)->[1]
        atomicAdd(&gz.psums[2 + r], vb);    // sum(b1)->[2], sum(b2)->[3]
    }
}

// ---------------- spmv_next(r): a[r][src] += pb[dst] (and mirror) -----------
__global__ void spmv_next_kernel(const int4* __restrict__ s2t,
                                 const int4* __restrict__ t2s, int r) {
    int i = blockIdx.x * blockDim.x + threadIdx.x;
    if (i < E4) {
        int4 s = __ldg(s2t + i);
        int4 d = __ldg(s2t + E4 + i);
        atomicAdd(&gz.a[r][s.x], __ldg(&g_pb[d.x]));
        atomicAdd(&gz.a[r][s.y], __ldg(&g_pb[d.y]));
        atomicAdd(&gz.a[r][s.z], __ldg(&g_pb[d.z]));
        atomicAdd(&gz.a[r][s.w], __ldg(&g_pb[d.w]));
    } else if (i < 2 * E4) {
        int e = i - E4;
        int4 s = __ldg(t2s + e);
        int4 d = __ldg(t2s + E4 + e);
        atomicAdd(&gz.b[r][s.x], __ldg(&g_pa[d.x]));
        atomicAdd(&gz.b[r][s.y], __ldg(&g_pa[d.y]));
        atomicAdd(&gz.b[r][s.z], __ldg(&g_pa[d.z]));
        atomicAdd(&gz.b[r][s.w], __ldg(&g_pa[d.w]));
    }
}

// ---------------- backward q-coefficient recursion (single block, 64 thr) ---
__global__ void qcoef_kernel(const float* __restrict__ Wl_s2t,
                             const float* __restrict__ b_s2t,
                             const float* __restrict__ Wr_s2t,
                             const float* __restrict__ Wl_t2s,
                             const float* __restrict__ b_t2s,
                             const float* __restrict__ Wr_t2s,
                             const float* __restrict__ lin_W) {
    __shared__ float QS[4][64], QT[4][64];
    __shared__ float red[64];
    int t = threadIdx.x;  // 64 threads

    float w = lin_W[t];
    #pragma unroll
    for (int k = 0; k < 4; k++) {
        QS[k][t] = (k == 0) ? w : 0.0f;
        QT[k][t] = (k == 0) ? w : 0.0f;
    }
    __syncthreads();

    float ss[4] = {(float)NSRC, gz.psums[0], gz.psums[1], 0.0f};
    float st[4] = {(float)NTGT, gz.psums[2], gz.psums[3], 0.0f};
    float acc = 0.0f;

    for (int l = 2; l >= 0; l--) {
        const float* A  = Wl_s2t + l * 4096;  // xt <- agg(xs)
        const float* B  = Wr_s2t + l * 4096;  // xt <- xt
        const float* C  = Wl_t2s + l * 4096;  // xs <- agg(xt)
        const float* Ew = Wr_t2s + l * 4096;  // xs <- xs
        float bsv = b_t2s[l * 64 + t];
        float btv = b_s2t[l * 64 + t];

        #pragma unroll
        for (int k = 0; k < 4; k++)
            acc += ss[k] * bsv * QS[k][t] + st[k] * btv * QT[k][t];

        float rs[4] = {0, 0, 0, 0}, rt[4] = {0, 0, 0, 0};
        for (int o = 0; o < 64; o++) {
            float ev = Ew[o * 64 + t];
            float av = A[o * 64 + t];
            float bv = B[o * 64 + t];
            float cv = C[o * 64 + t];
            rs[0] += ev * QS[0][o];
            rs[1] += ev * QS[1][o] + av * QT[0][o];
            rs[2] += ev * QS[2][o] + av * QT[1][o];
            rs[3] += ev * QS[3][o] + av * QT[2][o];
            rt[0] += bv * QT[0][o];
            rt[1] += bv * QT[1][o] + cv * QS[0][o];
            rt[2] += bv * QT[2][o] + cv * QS[1][o];
            rt[3] += bv * QT[3][o] + cv * QS[2][o];
        }
        __syncthreads();
        #pragma unroll
        for (int k = 0; k < 4; k++) { QS[k][t] = rs[k]; QT[k][t] = rt[k]; }
        __syncthreads();
    }

    #pragma unroll
    for (int k = 0; k < 4; k++) {
        g_Q[k][t]     = QS[k][t];
        g_Q[4 + k][t] = QT[k][t];
    }

    red[t] = acc;
    __syncthreads();
    if (t == 0) {
        float s = 0;
        #pragma unroll
        for (int i = 0; i < 64; i++) s += red[i];
        g_acc = s;
    }
}

// ---------------- final evaluation over the ORIGINAL inputs -----------------
__global__ void final_kernel(const float* __restrict__ xs,
                             const float* __restrict__ xt) {
    __shared__ float Q[8 * 64];
    __shared__ float partial[8];
    int tid = threadIdx.x;
    Q[tid] = ((const float*)g_Q)[tid];
    Q[tid + 256] = ((const float*)g_Q)[tid + 256];
    __syncthreads();

    int i = blockIdx.x * blockDim.x + tid;
    float v = 0.0f;
    if (i < NTOT) {
        bool is_s = (i < NSRC);
        int n = is_s ? i : i - NSRC;
        const float4* x = (const float4*)((is_s ? xs : xt) + (size_t)n * 64);
        const float4* Q0 = (const float4*)(Q + (is_s ? 0 : 256));
        const float4* Q1 = Q0 + 16;
        const float4* Q2 = Q0 + 32;
        const float4* Q3 = Q0 + 48;
        float c1 = is_s ? gz.a[0][n] : gz.b[0][n];
        float c2 = is_s ? gz.a[1][n] : gz.b[1][n];
        float c3 = is_s ? gz.a[2][n] : gz.b[2][n];
        #pragma unroll
        for (int j = 0; j < 16; j++) {
            float4 xv = __ldg(x + j);
            float4 q0 = Q0[j], q1 = Q1[j], q2 = Q2[j], q3 = Q3[j];
            v += xv.x * (q0.x + c1 * q1.x + c2 * q2.x + c3 * q3.x);
            v += xv.y * (q0.y + c1 * q1.y + c2 * q2.y + c3 * q3.y);
            v += xv.z * (q0.z + c1 * q1.z + c2 * q2.z + c3 * q3.z);
            v += xv.w * (q0.w + c1 * q1.w + c2 * q2.w + c3 * q3.w);
        }
    }
    #pragma unroll
    for (int off = 16; off; off >>= 1)
        v += __shfl_down_sync(0xffffffffu, v, off);
    if ((tid & 31) == 0) partial[tid >> 5] = v;
    __syncthreads();
    if (tid < 8) {
        float p = partial[tid];
        #pragma unroll
        for (int off = 4; off; off >>= 1)
            p += __shfl_down_sync(0xffu, p, off);
        if (tid == 0) atomicAdd(&gz.sum, p);
    }
}

__global__ void finalize_kernel(const float* __restrict__ lin_b,
                                float* __restrict__ out) {
    out[0] = (gz.sum + g_acc) * (1.0f / (float)NTOT) + lin_b[0];
}

// ---------------- launch ----------------------------------------------------
extern "C" void kernel_launch(void* const* d_in, const int* in_sizes, int n_in,
                              void* d_out, int out_size) {
    const float* x_source = (const float*)d_in[0];
    const float* x_target = (const float*)d_in[1];
    // d_in[2], d_in[3]: edge_attr (unused by the reference path)
    const float* W_l_s2t = (const float*)d_in[4];
    const float* b_s2t   = (const float*)d_in[5];
    const float* W_r_s2t = (const float*)d_in[6];
    const float* W_l_t2s = (const float*)d_in[7];
    const float* b_t2s   = (const float*)d_in[8];
    const float* W_r_t2s = (const float*)d_in[9];
    const float* lin_W   = (const float*)d_in[10];
    const float* lin_b   = (const float*)d_in[11];
    const int* ei_s2t    = (const int*)d_in[12];
    const int* ei_t2s    = (const int*)d_in[13];
    float* out = (float*)d_out;

    void* zb;
    cudaGetSymbolAddress(&zb, gz);
    cudaMemsetAsync(zb, 0, sizeof(ZeroBlock));   // ONE node zeroes everything

    const int4* s2t4 = (const int4*)ei_s2t;      // [0,E4): src, [E4,2E4): dst
    const int4* t2s4 = (const int4*)ei_t2s;

    const int eg = (2 * E4 + 255) / 256;         // 800K threads, 4 edges each
    const int ng = (NSRC + 255) / 256;

    deg_kernel<<<eg, 256>>>(s2t4 + E4, t2s4 + E4);
    spmv1_kernel<<<eg, 256>>>(s2t4, t2s4);            // a1, b1
    prep_kernel<<<ng, 256>>>(0);                       // pa/pb + sums(a1,b1)
    spmv_next_kernel<<<eg, 256>>>(s2t4, t2s4, 1);     // a2, b2
    prep_kernel<<<ng, 256>>>(1);                       // pa/pb + sums(a2,b2)
    spmv_next_kernel<<<eg, 256>>>(s2t4, t2s4, 2);     // a3, b3

    qcoef_kernel<<<1, 64>>>(W_l_s2t, b_s2t, W_r_s2t,
                            W_l_t2s, b_t2s, W_r_t2s, lin_W);
    final_kernel<<<(NTOT + 255) / 256, 256>>>(x_source, x_target);
    finalize_kernel<<<1, 1>>>(lin_b, out);
}

// round 10
// speedup vs baseline: 1.0037x; 1.0037x over previous
#include <cuda_runtime.h>

#define NSRC 100000
#define NTGT 100000
#define NEDGE 1600000
#define NTOT (NSRC + NTGT)
#define E4 (NEDGE / 4)

// ---------------- scratch: one contiguous zero-init block + rest ------------
struct ZeroBlock {
    int   deg_s[NSRC];
    int   deg_t[NTGT];
    float a[3][NSRC];   // a1,a2,a3 = S^T 1_t, S^T T^T 1_s, S^T T^T S^T 1_t
    float b[3][NTGT];   // b1,b2,b3 (mirror)
    float psums[4];     // sum(a1), sum(a2), sum(b1), sum(b2)
    float sum;          // final node-sum
};
__device__ ZeroBlock gz;
__device__ float g_pa[NSRC];     // a_r * inv_s (staging, fully overwritten)
__device__ float g_pb[NTGT];
__device__ float g_Q[8][64];     // level-0 coefficient vectors (fully written)
__device__ float g_acc;          // bias scalar contribution (fully written)

__device__ __forceinline__ float rcp_deg(int d) {
    return 1.0f / (float)max(d, 1);
}

// ---------------- degrees: 4 edges/thread, int4 dst loads -------------------
__global__ void deg_kernel(const int4* __restrict__ s2t_dst,
                           const int4* __restrict__ t2s_dst) {
    int i = blockIdx.x * blockDim.x + threadIdx.x;
    if (i < E4) {
        int4 d = __ldg(s2t_dst + i);
        atomicAdd(&gz.deg_t[d.x], 1);
        atomicAdd(&gz.deg_t[d.y], 1);
        atomicAdd(&gz.deg_t[d.z], 1);
        atomicAdd(&gz.deg_t[d.w], 1);
    } else if (i < 2 * E4) {
        int4 d = __ldg(t2s_dst + (i - E4));
        atomicAdd(&gz.deg_s[d.x], 1);
        atomicAdd(&gz.deg_s[d.y], 1);
        atomicAdd(&gz.deg_s[d.z], 1);
        atomicAdd(&gz.deg_s[d.w], 1);
    }
}

// ---------------- spmv1: a1[src] += rcp(deg_t[dst]) (and b1 mirror) ---------
__global__ void spmv1_kernel(const int4* __restrict__ s2t,
                             const int4* __restrict__ t2s) {
    int i = blockIdx.x * blockDim.x + threadIdx.x;
    if (i < E4) {
        int4 s = __ldg(s2t + i);
        int4 d = __ldg(s2t + E4 + i);
        float vx = rcp_deg(__ldg(&gz.deg_t[d.x]));
        float vy = rcp_deg(__ldg(&gz.deg_t[d.y]));
        float vz = rcp_deg(__ldg(&gz.deg_t[d.z]));
        float vw = rcp_deg(__ldg(&gz.deg_t[d.w]));
        atomicAdd(&gz.a[0][s.x], vx);
        atomicAdd(&gz.a[0][s.y], vy);
        atomicAdd(&gz.a[0][s.z], vz);
        atomicAdd(&gz.a[0][s.w], vw);
    } else if (i < 2 * E4) {
        int e = i - E4;
        int4 s = __ldg(t2s + e);
        int4 d = __ldg(t2s + E4 + e);
        float vx = rcp_deg(__ldg(&gz.deg_s[d.x]));
        float vy = rcp_deg(__ldg(&gz.deg_s[d.y]));
        float vz = rcp_deg(__ldg(&gz.deg_s[d.z]));
        float vw = rcp_deg(__ldg(&gz.deg_s[d.w]));
        atomicAdd(&gz.b[0][s.x], vx);
        atomicAdd(&gz.b[0][s.y], vy);
        atomicAdd(&gz.b[0][s.z], vz);
        atomicAdd(&gz.b[0][s.w], vw);
    }
}

// ---------------- prep(r): pa = a[r]*inv_s, pb = b[r]*inv_t, + fold sums ----
__global__ void prep_kernel(int r) {
    int i = blockIdx.x * blockDim.x + threadIdx.x;
    float va = 0.0f, vb = 0.0f;
    if (i < NSRC) {
        va = gz.a[r][i];
        g_pa[i] = va * rcp_deg(gz.deg_s[i]);
    }
    if (i < NTGT) {
        vb = gz.b[r][i];
        g_pb[i] = vb * rcp_deg(gz.deg_t[i]);
    }
    #pragma unroll
    for (int off = 16; off; off >>= 1) {
        va += __shfl_down_sync(0xffffffffu, va, off);
        vb += __shfl_down_sync(0xffffffffu, vb, off);
    }
    if ((threadIdx.x & 31) == 0) {
        atomicAdd(&gz.psums[r], va);        // sum(a1)->[0], sum(a2)->[1]
        atomicAdd(&gz.psums[2 + r], vb);    // sum(b1)->[2], sum(b2)->[3]
    }
}

// ---------------- spmv_next(r): a[r][src] += pb[dst] (and mirror) -----------
__global__ void spmv_next_kernel(const int4* __restrict__ s2t,
                                 const int4* __restrict__ t2s, int r) {
    int i = blockIdx.x * blockDim.x + threadIdx.x;
    if (i < E4) {
        int4 s = __ldg(s2t + i);
        int4 d = __ldg(s2t + E4 + i);
        atomicAdd(&gz.a[r][s.x], __ldg(&g_pb[d.x]));
        atomicAdd(&gz.a[r][s.y], __ldg(&g_pb[d.y]));
        atomicAdd(&gz.a[r][s.z], __ldg(&g_pb[d.z]));
        atomicAdd(&gz.a[r][s.w], __ldg(&g_pb[d.w]));
    } else if (i < 2 * E4) {
        int e = i - E4;
        int4 s = __ldg(t2s + e);
        int4 d = __ldg(t2s + E4 + e);
        atomicAdd(&gz.b[r][s.x], __ldg(&g_pa[d.x]));
        atomicAdd(&gz.b[r][s.y], __ldg(&g_pa[d.y]));
        atomicAdd(&gz.b[r][s.z], __ldg(&g_pa[d.z]));
        atomicAdd(&gz.b[r][s.w], __ldg(&g_pa[d.w]));
    }
}

// ---------------- backward q-coefficient recursion (single block, 64 thr) ---
__global__ void qcoef_kernel(const float* __restrict__ Wl_s2t,
                             const float* __restrict__ b_s2t,
                             const float* __restrict__ Wr_s2t,
                             const float* __restrict__ Wl_t2s,
                             const float* __restrict__ b_t2s,
                             const float* __restrict__ Wr_t2s,
                             const float* __restrict__ lin_W) {
    __shared__ float QS[4][64], QT[4][64];
    __shared__ float red[64];
    int t = threadIdx.x;  // 64 threads

    float w = lin_W[t];
    #pragma unroll
    for (int k = 0; k < 4; k++) {
        QS[k][t] = (k == 0) ? w : 0.0f;
        QT[k][t] = (k == 0) ? w : 0.0f;
    }
    __syncthreads();

    float ss[4] = {(float)NSRC, gz.psums[0], gz.psums[1], 0.0f};
    float st[4] = {(float)NTGT, gz.psums[2], gz.psums[3], 0.0f};
    float acc = 0.0f;

    for (int l = 2; l >= 0; l--) {
        const float* A  = Wl_s2t + l * 4096;  // xt <- agg(xs)
        const float* B  = Wr_s2t + l * 4096;  // xt <- xt
        const float* C  = Wl_t2s + l * 4096;  // xs <- agg(xt)
        const float* Ew = Wr_t2s + l * 4096;  // xs <- xs
        float bsv = b_t2s[l * 64 + t];
        float btv = b_s2t[l * 64 + t];

        #pragma unroll
        for (int k = 0; k < 4; k++)
            acc += ss[k] * bsv * QS[k][t] + st[k] * btv * QT[k][t];

        float rs[4] = {0, 0, 0, 0}, rt[4] = {0, 0, 0, 0};
        for (int o = 0; o < 64; o++) {
            float ev = Ew[o * 64 + t];
            float av = A[o * 64 + t];
            float bv = B[o * 64 + t];
            float cv = C[o * 64 + t];
            rs[0] += ev * QS[0][o];
            rs[1] += ev * QS[1][o] + av * QT[0][o];
            rs[2] += ev * QS[2][o] + av * QT[1][o];
            rs[3] += ev * QS[3][o] + av * QT[2][o];
            rt[0] += bv * QT[0][o];
            rt[1] += bv * QT[1][o] + cv * QS[0][o];
            rt[2] += bv * QT[2][o] + cv * QS[1][o];
            rt[3] += bv * QT[3][o] + cv * QS[2][o];
        }
        __syncthreads();
        #pragma unroll
        for (int k = 0; k < 4; k++) { QS[k][t] = rs[k]; QT[k][t] = rt[k]; }
        __syncthreads();
    }

    #pragma unroll
    for (int k = 0; k < 4; k++) {
        g_Q[k][t]     = QS[k][t];
        g_Q[4 + k][t] = QT[k][t];
    }

    red[t] = acc;
    __syncthreads();
    if (t == 0) {
        float s = 0;
        #pragma unroll
        for (int i = 0; i < 64; i++) s += red[i];
        g_acc = s;
    }
}

// ---------------- final evaluation over the ORIGINAL inputs -----------------
__global__ void final_kernel(const float* __restrict__ xs,
                             const float* __restrict__ xt) {
    __shared__ float Q[8 * 64];
    __shared__ float partial[8];
    int tid = threadIdx.x;
    Q[tid] = ((const float*)g_Q)[tid];
    Q[tid + 256] = ((const float*)g_Q)[tid + 256];
    __syncthreads();

    int i = blockIdx.x * blockDim.x + tid;
    float v = 0.0f;
    if (i < NTOT) {
        bool is_s = (i < NSRC);
        int n = is_s ? i : i - NSRC;
        const float4* x = (const float4*)((is_s ? xs : xt) + (size_t)n * 64);
        const float4* Q0 = (const float4*)(Q + (is_s ? 0 : 256));
        const float4* Q1 = Q0 + 16;
        const float4* Q2 = Q0 + 32;
        const float4* Q3 = Q0 + 48;
        float c1 = is_s ? gz.a[0][n] : gz.b[0][n];
        float c2 = is_s ? gz.a[1][n] : gz.b[1][n];
        float c3 = is_s ? gz.a[2][n] : gz.b[2][n];
        #pragma unroll
        for (int j = 0; j < 16; j++) {
            float4 xv = __ldg(x + j);
            float4 q0 = Q0[j], q1 = Q1[j], q2 = Q2[j], q3 = Q3[j];
            v += xv.x * (q0.x + c1 * q1.x + c2 * q2.x + c3 * q3.x);
            v += xv.y * (q0.y + c1 * q1.y + c2 * q2.y + c3 * q3.y);
            v += xv.z * (q0.z + c1 * q1.z + c2 * q2.z + c3 * q3.z);
            v += xv.w * (q0.w + c1 * q1.w + c2 * q2.w + c3 * q3.w);
        }
    }
    #pragma unroll
    for (int off = 16; off; off >>= 1)
        v += __shfl_down_sync(0xffffffffu, v, off);
    if ((tid & 31) == 0) partial[tid >> 5] = v;
    __syncthreads();
    if (tid < 8) {
        float p = partial[tid];
        #pragma unroll
        for (int off = 4; off; off >>= 1)
            p += __shfl_down_sync(0xffu, p, off);
        if (tid == 0) atomicAdd(&gz.sum, p);
    }
}

__global__ void finalize_kernel(const float* __restrict__ lin_b,
                                float* __restrict__ out) {
    out[0] = (gz.sum + g_acc) * (1.0f / (float)NTOT) + lin_b[0];
}

// ---------------- launch ----------------------------------------------------
extern "C" void kernel_launch(void* const* d_in, const int* in_sizes, int n_in,
                              void* d_out, int out_size) {
    const float* x_source = (const float*)d_in[0];
    const float* x_target = (const float*)d_in[1];
    // d_in[2], d_in[3]: edge_attr (unused by the reference path)
    const float* W_l_s2t = (const float*)d_in[4];
    const float* b_s2t   = (const float*)d_in[5];
    const float* W_r_s2t = (const float*)d_in[6];
    const float* W_l_t2s = (const float*)d_in[7];
    const float* b_t2s   = (const float*)d_in[8];
    const float* W_r_t2s = (const float*)d_in[9];
    const float* lin_W   = (const float*)d_in[10];
    const float* lin_b   = (const float*)d_in[11];
    const int* ei_s2t    = (const int*)d_in[12];
    const int* ei_t2s    = (const int*)d_in[13];
    float* out = (float*)d_out;

    void* zb;
    cudaGetSymbolAddress(&zb, gz);
    cudaMemsetAsync(zb, 0, sizeof(ZeroBlock));   // ONE node zeroes everything

    const int4* s2t4 = (const int4*)ei_s2t;      // [0,E4): src, [E4,2E4): dst
    const int4* t2s4 = (const int4*)ei_t2s;

    const int eg = (2 * E4 + 255) / 256;         // 800K threads, 4 edges each
    const int ng = (NSRC + 255) / 256;

    deg_kernel<<<eg, 256>>>(s2t4 + E4, t2s4 + E4);
    spmv1_kernel<<<eg, 256>>>(s2t4, t2s4);            // a1, b1
    prep_kernel<<<ng, 256>>>(0);                       // pa/pb + sums(a1,b1)
    spmv_next_kernel<<<eg, 256>>>(s2t4, t2s4, 1);     // a2, b2
    prep_kernel<<<ng, 256>>>(1);                       // pa/pb + sums(a2,b2)
    spmv_next_kernel<<<eg, 256>>>(s2t4, t2s4, 2);     // a3, b3

    qcoef_kernel<<<1, 64>>>(W_l_s2t, b_s2t, W_r_s2t,
                            W_l_t2s, b_t2s, W_r_t2s, lin_W);
    final_kernel<<<(NTOT + 255) / 256, 256>>>(x_source, x_target);
    finalize_kernel<<<1, 1>>>(lin_b, out);
}